// round 6
// baseline (speedup 1.0000x reference)
#include <cuda_runtime.h>
#include <cstdint>

// VisibilityHeatmap: out[b,k] = in_bounds(coords[b,k]) && heatmaps[b,k,v,u] > 0.4
// coords: [B,K,2] int32 in (u,v) order; heatmaps: [B,K,H,W] f32.
// Output: [B,K] boolean mask as float32 (0.0f / 1.0f).
//
// 2 outputs per thread: one int4 coord load -> two independent gathers -> one
// float2 store. 4096 threads = 32 blocks x 128 (R2's best block count with half
// the per-SM wavefront load). Minimal SASS body; 32-bit offset arithmetic.
#define B_DIM 128
#define K_DIM 64
#define H_DIM 128
#define W_DIM 128
#define PLANE (H_DIM * W_DIM)     // 16384
#define THRESH 0.4f

__global__ __launch_bounds__(128)
void visibility_kernel(const int4* __restrict__ coords2,   // one int4 = 2 (u,v) pairs
                       const float* __restrict__ heatmaps,
                       float2* __restrict__ out2)
{
    unsigned t = blockIdx.x * 128u + threadIdx.x;   // 0..4095, outputs [2t, 2t+2)

    int4 c = coords2[t];            // (u0, v0, u1, v1)
    int u0 = c.x, v0 = c.y;
    int u1 = c.z, v1 = c.w;

    bool ib0 = (v0 > -1) & (u0 > -1) & (v0 < H_DIM) & (u0 < W_DIM);
    bool ib1 = (v1 > -1) & (u1 > -1) & (v1 < H_DIM) & (u1 < W_DIM);

    unsigned base = 2u * t * PLANE;     // element offset, max 2^27 — fits u32
    unsigned off0 = base
                  + (unsigned)(min(max(v0, 0), H_DIM - 1) * W_DIM + min(max(u0, 0), W_DIM - 1));
    unsigned off1 = base + PLANE
                  + (unsigned)(min(max(v1, 0), H_DIM - 1) * W_DIM + min(max(u1, 0), W_DIM - 1));

    // two independent gathers — issued back-to-back, latency overlapped
    float f0 = __ldg(heatmaps + off0);
    float f1 = __ldg(heatmaps + off1);

    float2 r;
    r.x = (ib0 && (f0 > THRESH)) ? 1.0f : 0.0f;
    r.y = (ib1 && (f1 > THRESH)) ? 1.0f : 0.0f;
    out2[t] = r;
}

extern "C" void kernel_launch(void* const* d_in, const int* in_sizes, int n_in,
                              void* d_out, int out_size)
{
    const int4*  coords2  = (const int4*)d_in[0];    // [B,K,2] int32, 2 pairs per int4
    const float* heatmaps = (const float*)d_in[1];   // [B,K,H,W] f32
    float2*      out2     = (float2*)d_out;          // [B,K] mask as f32, 2 per store

    // 8192 outputs / 2 per thread = 4096 threads = 32 blocks x 128
    visibility_kernel<<<32, 128>>>(coords2, heatmaps, out2);
}